// round 6
// baseline (speedup 1.0000x reference)
#include <cuda_runtime.h>
#include <cuda_fp16.h>

#define NN   50000
#define EE   800000
#define INC  128
#define HID  96
#define OUTC 40
#define SLOPE 0.2f

// ---------------- scratch (device globals; no allocation allowed) ----------
__device__ __half g_h1[(size_t)NN * HID];    // fp16 features (gather-only)
__device__ __half g_h2[(size_t)NN * OUTC];
__device__ float  g_agg1[(size_t)NN * HID];  // normalized layer-1 aggregation
__device__ float  g_agg2[(size_t)NN * OUTC]; // normalized layer-2 aggregation
__device__ float  g_as1[NN], g_ad1[NN];
__device__ float  g_as2[NN], g_ad2[NN];
__device__ int    g_cnt[NN];
__device__ int    g_off[NN + 1];
__device__ int    g_cur[NN];
__device__ int    g_csr[EE];

// ---------------- zero pass --------------------------------------------------
__global__ void k_zero() {
    int i = blockIdx.x * blockDim.x + threadIdx.x;
    if (i < NN) {
        g_cnt[i] = 0;
        g_as1[i] = 0.f; g_ad1[i] = 0.f;
        g_as2[i] = 0.f; g_ad2[i] = 0.f;
    }
}

// ---------------- CSR build --------------------------------------------------
__global__ void k_hist(const int* __restrict__ ei) {
    int i = blockIdx.x * blockDim.x + threadIdx.x;
    if (i < EE) atomicAdd(&g_cnt[ei[EE + i]], 1);
}

// single-block fused exclusive scan over g_cnt -> g_off, g_cur
__global__ void k_scan() {
    __shared__ int sm[1024];
    const int tid = threadIdx.x;
    const int PT = (NN + 1023) / 1024;      // 49
    int b = tid * PT;
    int e = min(b + PT, NN);
    int s = 0;
    for (int i = b; i < e; i++) s += g_cnt[i];
    sm[tid] = s;
    __syncthreads();
#pragma unroll
    for (int o = 1; o < 1024; o <<= 1) {
        int t = (tid >= o) ? sm[tid - o] : 0;
        __syncthreads();
        sm[tid] += t;
        __syncthreads();
    }
    int run = sm[tid] - s;                   // exclusive prefix for this range
    for (int i = b; i < e; i++) {
        int c = g_cnt[i];
        g_off[i] = run;
        g_cur[i] = run;
        run += c;
    }
    if (tid == 1023) g_off[NN] = EE;
}

__global__ void k_fill(const int* __restrict__ ei) {
    int i = blockIdx.x * blockDim.x + threadIdx.x;
    if (i >= EE) return;
    int d = ei[EE + i];
    int pos = atomicAdd(&g_cur[d], 1);
    g_csr[pos] = ei[i];
}

// ---------------- tiled GEMM: H[n,CO] = X[n,K] @ W[K,CO] --------------------
// Stores H in fp16 (consumed only by the CSR gather). Epilogue fuses per-node
// attention scalars (atomicAdd partials, from fp32 accumulators).
// Optional fused relu(x + bias) on the X-tile load (layer-2 input).
template <int K, int CO, int TM, int TCOLS, int TROWS, bool FUSE>
__global__ void k_gemm_t(const float* __restrict__ X, const float* __restrict__ W,
                         const float* __restrict__ bias,
                         const float* __restrict__ asrc, const float* __restrict__ adst,
                         float* __restrict__ oas, float* __restrict__ oad,
                         __half* __restrict__ H, int n) {
    constexpr int KT = 32;
    constexpr int THREADS = TCOLS * TROWS;
    constexpr int RPT = TM / TROWS;
    __shared__ float Xs[TM][KT];
    __shared__ float Ws[KT][CO];

    const int tid  = threadIdx.x;
    const int tcol = tid % TCOLS;
    const int trow = tid / TCOLS;
    const int row0 = blockIdx.x * TM;

    float4 acc[RPT];
#pragma unroll
    for (int i = 0; i < RPT; i++) acc[i] = make_float4(0.f, 0.f, 0.f, 0.f);

    for (int kt = 0; kt < K; kt += KT) {
        for (int idx = tid; idx < TM * (KT / 4); idx += THREADS) {
            int r  = idx / (KT / 4);
            int c4 = idx % (KT / 4);
            int grow = row0 + r;
            float4 v = make_float4(0.f, 0.f, 0.f, 0.f);
            if (grow < n) {
                v = *(const float4*)(X + (size_t)grow * K + kt + c4 * 4);
                if constexpr (FUSE) {
                    const float* bb = bias + kt + c4 * 4;
                    v.x = fmaxf(v.x + bb[0], 0.f);
                    v.y = fmaxf(v.y + bb[1], 0.f);
                    v.z = fmaxf(v.z + bb[2], 0.f);
                    v.w = fmaxf(v.w + bb[3], 0.f);
                }
            }
            *(float4*)&Xs[r][c4 * 4] = v;
        }
        for (int idx = tid; idx < KT * (CO / 4); idx += THREADS) {
            int r  = idx / (CO / 4);
            int c4 = idx % (CO / 4);
            *(float4*)&Ws[r][c4 * 4] =
                *(const float4*)(W + (size_t)(kt + r) * CO + c4 * 4);
        }
        __syncthreads();

#pragma unroll
        for (int k4 = 0; k4 < KT; k4 += 4) {
            float4 xs[RPT];
#pragma unroll
            for (int i = 0; i < RPT; i++)
                xs[i] = *(float4*)&Xs[trow * RPT + i][k4];
#pragma unroll
            for (int kk = 0; kk < 4; kk++) {
                float4 w = *(float4*)&Ws[k4 + kk][tcol * 4];
#pragma unroll
                for (int i = 0; i < RPT; i++) {
                    float xv = (kk == 0) ? xs[i].x : (kk == 1) ? xs[i].y
                             : (kk == 2) ? xs[i].z : xs[i].w;
                    acc[i].x += xv * w.x; acc[i].y += xv * w.y;
                    acc[i].z += xv * w.z; acc[i].w += xv * w.w;
                }
            }
        }
        __syncthreads();
    }

    float4 vs = *(const float4*)(asrc + tcol * 4);
    float4 vd = *(const float4*)(adst + tcol * 4);
#pragma unroll
    for (int i = 0; i < RPT; i++) {
        int grow = row0 + trow * RPT + i;
        if (grow < n) {
            __half2* hrow = (__half2*)(H + (size_t)grow * CO) + tcol * 2;
            hrow[0] = __floats2half2_rn(acc[i].x, acc[i].y);
            hrow[1] = __floats2half2_rn(acc[i].z, acc[i].w);
            float ps = acc[i].x * vs.x + acc[i].y * vs.y + acc[i].z * vs.z + acc[i].w * vs.w;
            float pd = acc[i].x * vd.x + acc[i].y * vd.y + acc[i].z * vd.z + acc[i].w * vd.w;
            atomicAdd(&oas[grow], ps);
            atomicAdd(&oad[grow], pd);
        }
    }
}

// ---------------- CSR gather aggregation: one warp per dst node --------------
// out[node] = (w_self*h[node] + sum_e w_e*h[src_e]) / (w_self + sum_e w_e)
template <int C>
__global__ void k_agg_csr(const __half* __restrict__ h,
                          const float* __restrict__ as,
                          const float* __restrict__ ad,
                          float* __restrict__ aggout) {
    constexpr int CPL = (C + 31) / 32;   // channels per lane
    int node = blockIdx.x * (blockDim.x >> 5) + (threadIdx.x >> 5);
    int lane = threadIdx.x & 31;
    if (node >= NN) return;

    float ad_n = ad[node];
    float as_n = as[node];
    float vself = as_n + ad_n;
    vself = (vself > 0.f) ? vself : SLOPE * vself;
    float wself = __expf(vself);

    float acc[CPL];
#pragma unroll
    for (int j = 0; j < CPL; j++) {
        int c = lane + 32 * j;
        acc[j] = (c < C) ? wself * __half2float(h[(size_t)node * C + c]) : 0.f;
    }

    int beg = g_off[node];
    int end = g_off[node + 1];
    float sloc = 0.f;

    for (int base = beg; base < end; base += 32) {
        int e = base + lane;
        bool valid = e < end;
        int src = valid ? g_csr[e] : 0;
        float w = 0.f;
        if (valid) {
            float v = as[src] + ad_n;
            v = (v > 0.f) ? v : SLOPE * v;
            w = __expf(v);
        }
        sloc += w;
        int cnt = min(32, end - base);
        for (int k = 0; k < cnt; k++) {
            float wk = __shfl_sync(0xffffffffu, w, k);
            int   sk = __shfl_sync(0xffffffffu, src, k);
            const __half* hr = h + (size_t)sk * C;
#pragma unroll
            for (int j = 0; j < CPL; j++) {
                int c = lane + 32 * j;
                if (c < C) acc[j] += wk * __half2float(hr[c]);
            }
        }
    }

    // total weight
#pragma unroll
    for (int o = 16; o; o >>= 1) sloc += __shfl_xor_sync(0xffffffffu, sloc, o);
    float inv = 1.f / (sloc + wself);

#pragma unroll
    for (int j = 0; j < CPL; j++) {
        int c = lane + 32 * j;
        if (c < C) aggout[(size_t)node * C + c] = acc[j] * inv;
    }
}

// ---------------- bias + log_softmax (final output), one warp per node ------
__global__ void k_out(const float* __restrict__ agg, const float* __restrict__ b,
                      float* __restrict__ out) {
    int gw = (blockIdx.x * blockDim.x + threadIdx.x) >> 5;
    int lane = threadIdx.x & 31;
    if (gw >= NN) return;
    const float* row = agg + (size_t)gw * OUTC;
    float z0 = row[lane] + b[lane];
    bool v1 = lane < (OUTC - 32);
    float z1 = v1 ? (row[32 + lane] + b[32 + lane]) : -3.4e38f;
    float mx = fmaxf(z0, z1);
#pragma unroll
    for (int o = 16; o; o >>= 1) mx = fmaxf(mx, __shfl_xor_sync(0xffffffffu, mx, o));
    float sm = __expf(z0 - mx) + (v1 ? __expf(z1 - mx) : 0.f);
#pragma unroll
    for (int o = 16; o; o >>= 1) sm += __shfl_xor_sync(0xffffffffu, sm, o);
    float lse = mx + __logf(sm);
    out[(size_t)gw * OUTC + lane] = z0 - lse;
    if (v1) out[(size_t)gw * OUTC + 32 + lane] = z1 - lse;
}

// ---------------- launch -----------------------------------------------------
static inline int cdiv(long long a, int b) { return (int)((a + b - 1) / b); }

extern "C" void kernel_launch(void* const* d_in, const int* in_sizes, int n_in,
                              void* d_out, int out_size) {
    const float* x    = (const float*)d_in[0];
    const int*   ei   = (const int*)d_in[1];   // int32 (JAX x64 disabled)
    // d_in[2] = new_edge_indexs — unused by the reference
    const float* W1   = (const float*)d_in[3];
    const float* asr1 = (const float*)d_in[4];
    const float* ads1 = (const float*)d_in[5];
    const float* b1   = (const float*)d_in[6];
    const float* W2   = (const float*)d_in[7];
    const float* asr2 = (const float*)d_in[8];
    const float* ads2 = (const float*)d_in[9];
    const float* b2   = (const float*)d_in[10];
    float* out = (float*)d_out;

    __half *h1, *h2;
    float *agg1, *agg2, *as1, *ad1, *as2, *ad2;
    cudaGetSymbolAddress((void**)&h1, g_h1);
    cudaGetSymbolAddress((void**)&h2, g_h2);
    cudaGetSymbolAddress((void**)&agg1, g_agg1);
    cudaGetSymbolAddress((void**)&agg2, g_agg2);
    cudaGetSymbolAddress((void**)&as1, g_as1);
    cudaGetSymbolAddress((void**)&ad1, g_ad1);
    cudaGetSymbolAddress((void**)&as2, g_as2);
    cudaGetSymbolAddress((void**)&ad2, g_ad2);

    const int T = 256;

    // ---- CSR build (once, reused by both layers) ----
    k_zero<<<cdiv(NN, T), T>>>();
    k_hist<<<cdiv(EE, T), T>>>(ei);
    k_scan<<<1, 1024>>>();
    k_fill<<<cdiv(EE, T), T>>>(ei);

    // ---- layer 1 ----
    k_gemm_t<INC, HID, 64, 24, 8, false>
        <<<cdiv(NN, 64), 24 * 8>>>(x, W1, nullptr, asr1, ads1, as1, ad1, h1, NN);
    k_agg_csr<HID><<<cdiv(NN, 8), 256>>>(h1, as1, ad1, agg1);

    // ---- layer 2 ----
    k_gemm_t<HID, OUTC, 128, 10, 16, true>
        <<<cdiv(NN, 128), 10 * 16>>>(agg1, W2, b1, asr2, ads2, as2, ad2, h2, NN);
    k_agg_csr<OUTC><<<cdiv(NN, 8), 256>>>(h2, as2, ad2, agg2);
    k_out<<<cdiv((long long)NN * 32, T), T>>>(agg2, b2, out);
}

// round 7
// speedup vs baseline: 1.0617x; 1.0617x over previous
#include <cuda_runtime.h>

#define NN   50000
#define EE   800000
#define INC  128
#define HID  96
#define OUTC 40
#define SLOPE 0.2f

// ---------------- scratch (device globals; no allocation allowed) ----------
__device__ float g_h1[(size_t)NN * HID];
__device__ float g_h2[(size_t)NN * OUTC];
__device__ float g_agg1[(size_t)NN * HID];   // normalized layer-1 aggregation
__device__ float g_agg2[(size_t)NN * OUTC];  // normalized layer-2 aggregation
__device__ float g_as1[NN], g_ad1[NN];
__device__ float g_as2[NN], g_ad2[NN];
__device__ int   g_cnt[NN];
__device__ int   g_off[NN + 1];
__device__ int   g_cur[NN];
__device__ int   g_csr[EE];

// ---------------- zero pass (counts only) ------------------------------------
__global__ void k_zero() {
    int i = blockIdx.x * blockDim.x + threadIdx.x;
    if (i < NN) g_cnt[i] = 0;
}

// ---------------- CSR build --------------------------------------------------
__global__ void k_hist(const int* __restrict__ ei) {
    int i = blockIdx.x * blockDim.x + threadIdx.x;
    if (i < EE) atomicAdd(&g_cnt[ei[EE + i]], 1);
}

// single-block fused exclusive scan over g_cnt -> g_off, g_cur
__global__ void k_scan() {
    __shared__ int sm[1024];
    const int tid = threadIdx.x;
    const int PT = (NN + 1023) / 1024;      // 49
    int b = tid * PT;
    int e = min(b + PT, NN);
    int s = 0;
    for (int i = b; i < e; i++) s += g_cnt[i];
    sm[tid] = s;
    __syncthreads();
#pragma unroll
    for (int o = 1; o < 1024; o <<= 1) {
        int t = (tid >= o) ? sm[tid - o] : 0;
        __syncthreads();
        sm[tid] += t;
        __syncthreads();
    }
    int run = sm[tid] - s;                   // exclusive prefix for this range
    for (int i = b; i < e; i++) {
        int c = g_cnt[i];
        g_off[i] = run;
        g_cur[i] = run;
        run += c;
    }
    if (tid == 1023) g_off[NN] = EE;
}

__global__ void k_fill(const int* __restrict__ ei) {
    int i = blockIdx.x * blockDim.x + threadIdx.x;
    if (i >= EE) return;
    int d = ei[EE + i];
    int pos = atomicAdd(&g_cur[d], 1);
    g_csr[pos] = ei[i];
}

// ---------------- tiled GEMM: H[n,CO] = X[n,K] @ W[K,CO] --------------------
// Epilogue fuses per-node attention scalars via smem cross-column reduction
// (direct store, no atomics, no zero-init needed).
// Optional fused relu(x + bias) on the X-tile load (layer-2 input).
template <int K, int CO, int TM, int TCOLS, int TROWS, bool FUSE>
__global__ void k_gemm_t(const float* __restrict__ X, const float* __restrict__ W,
                         const float* __restrict__ bias,
                         const float* __restrict__ asrc, const float* __restrict__ adst,
                         float* __restrict__ oas, float* __restrict__ oad,
                         float* __restrict__ H, int n) {
    constexpr int KT = 32;
    constexpr int THREADS = TCOLS * TROWS;
    constexpr int RPT = TM / TROWS;
    __shared__ float Xs[TM][KT];
    __shared__ float Ws[KT][CO];
    __shared__ float Ps[TM][TCOLS];
    __shared__ float Pd[TM][TCOLS];

    const int tid  = threadIdx.x;
    const int tcol = tid % TCOLS;
    const int trow = tid / TCOLS;
    const int row0 = blockIdx.x * TM;

    float4 acc[RPT];
#pragma unroll
    for (int i = 0; i < RPT; i++) acc[i] = make_float4(0.f, 0.f, 0.f, 0.f);

    for (int kt = 0; kt < K; kt += KT) {
        for (int idx = tid; idx < TM * (KT / 4); idx += THREADS) {
            int r  = idx / (KT / 4);
            int c4 = idx % (KT / 4);
            int grow = row0 + r;
            float4 v = make_float4(0.f, 0.f, 0.f, 0.f);
            if (grow < n) {
                v = *(const float4*)(X + (size_t)grow * K + kt + c4 * 4);
                if constexpr (FUSE) {
                    const float* bb = bias + kt + c4 * 4;
                    v.x = fmaxf(v.x + bb[0], 0.f);
                    v.y = fmaxf(v.y + bb[1], 0.f);
                    v.z = fmaxf(v.z + bb[2], 0.f);
                    v.w = fmaxf(v.w + bb[3], 0.f);
                }
            }
            *(float4*)&Xs[r][c4 * 4] = v;
        }
        for (int idx = tid; idx < KT * (CO / 4); idx += THREADS) {
            int r  = idx / (CO / 4);
            int c4 = idx % (CO / 4);
            *(float4*)&Ws[r][c4 * 4] =
                *(const float4*)(W + (size_t)(kt + r) * CO + c4 * 4);
        }
        __syncthreads();

#pragma unroll
        for (int k4 = 0; k4 < KT; k4 += 4) {
            float4 xs[RPT];
#pragma unroll
            for (int i = 0; i < RPT; i++)
                xs[i] = *(float4*)&Xs[trow * RPT + i][k4];
#pragma unroll
            for (int kk = 0; kk < 4; kk++) {
                float4 w = *(float4*)&Ws[k4 + kk][tcol * 4];
#pragma unroll
                for (int i = 0; i < RPT; i++) {
                    float xv = (kk == 0) ? xs[i].x : (kk == 1) ? xs[i].y
                             : (kk == 2) ? xs[i].z : xs[i].w;
                    acc[i].x += xv * w.x; acc[i].y += xv * w.y;
                    acc[i].z += xv * w.z; acc[i].w += xv * w.w;
                }
            }
        }
        __syncthreads();
    }

    // ---- epilogue: store H; per-row attention scalars via smem reduction ----
    float4 vs = *(const float4*)(asrc + tcol * 4);
    float4 vd = *(const float4*)(adst + tcol * 4);
#pragma unroll
    for (int i = 0; i < RPT; i++) {
        int r = trow * RPT + i;
        int grow = row0 + r;
        if (grow < n)
            *(float4*)(H + (size_t)grow * CO + tcol * 4) = acc[i];
        Ps[r][tcol] = acc[i].x * vs.x + acc[i].y * vs.y + acc[i].z * vs.z + acc[i].w * vs.w;
        Pd[r][tcol] = acc[i].x * vd.x + acc[i].y * vd.y + acc[i].z * vd.z + acc[i].w * vd.w;
    }
    __syncthreads();
    for (int r = tid; r < TM; r += THREADS) {
        int grow = row0 + r;
        if (grow < n) {
            float ss = 0.f, sd = 0.f;
#pragma unroll
            for (int c = 0; c < TCOLS; c++) { ss += Ps[r][c]; sd += Pd[r][c]; }
            oas[grow] = ss;
            oad[grow] = sd;
        }
    }
}

// ---------------- CSR gather aggregation: one warp per dst node --------------
// float4 lanes: lanes 0..C/4-1 each own 4 channels -> 1 LDG.128 per neighbor.
// out[node] = (w_self*h[node] + sum_e w_e*h[src_e]) / (w_self + sum_e w_e)
template <int C>
__global__ void k_agg_csr(const float* __restrict__ h,
                          const float* __restrict__ as,
                          const float* __restrict__ ad,
                          float* __restrict__ aggout) {
    constexpr int V4 = C / 4;            // active gather lanes (24 or 10)
    int node = blockIdx.x * (blockDim.x >> 5) + (threadIdx.x >> 5);
    int lane = threadIdx.x & 31;
    if (node >= NN) return;

    float ad_n = ad[node];
    float vself = as[node] + ad_n;
    vself = (vself > 0.f) ? vself : SLOPE * vself;
    float wself = __expf(vself);

    float4 acc = make_float4(0.f, 0.f, 0.f, 0.f);
    if (lane < V4) {
        float4 hv = *(const float4*)(h + (size_t)node * C + lane * 4);
        acc.x = wself * hv.x; acc.y = wself * hv.y;
        acc.z = wself * hv.z; acc.w = wself * hv.w;
    }

    int beg = g_off[node];
    int end = g_off[node + 1];
    float sloc = 0.f;

    for (int base = beg; base < end; base += 32) {
        int e = base + lane;
        bool valid = e < end;
        int src = valid ? g_csr[e] : 0;
        float w = 0.f;
        if (valid) {
            float v = as[src] + ad_n;
            v = (v > 0.f) ? v : SLOPE * v;
            w = __expf(v);
        }
        sloc += w;
        int cnt = min(32, end - base);
        for (int k = 0; k < cnt; k++) {
            float wk = __shfl_sync(0xffffffffu, w, k);
            int   sk = __shfl_sync(0xffffffffu, src, k);
            if (lane < V4) {
                float4 hv = *(const float4*)(h + (size_t)sk * C + lane * 4);
                acc.x += wk * hv.x; acc.y += wk * hv.y;
                acc.z += wk * hv.z; acc.w += wk * hv.w;
            }
        }
    }

#pragma unroll
    for (int o = 16; o; o >>= 1) sloc += __shfl_xor_sync(0xffffffffu, sloc, o);
    float inv = 1.f / (sloc + wself);

    if (lane < V4) {
        float4 r = make_float4(acc.x * inv, acc.y * inv, acc.z * inv, acc.w * inv);
        *(float4*)(aggout + (size_t)node * C + lane * 4) = r;
    }
}

// ---------------- bias + log_softmax (final output), one warp per node ------
__global__ void k_out(const float* __restrict__ agg, const float* __restrict__ b,
                      float* __restrict__ out) {
    int gw = (blockIdx.x * blockDim.x + threadIdx.x) >> 5;
    int lane = threadIdx.x & 31;
    if (gw >= NN) return;
    const float* row = agg + (size_t)gw * OUTC;
    float z0 = row[lane] + b[lane];
    bool v1 = lane < (OUTC - 32);
    float z1 = v1 ? (row[32 + lane] + b[32 + lane]) : -3.4e38f;
    float mx = fmaxf(z0, z1);
#pragma unroll
    for (int o = 16; o; o >>= 1) mx = fmaxf(mx, __shfl_xor_sync(0xffffffffu, mx, o));
    float sm = __expf(z0 - mx) + (v1 ? __expf(z1 - mx) : 0.f);
#pragma unroll
    for (int o = 16; o; o >>= 1) sm += __shfl_xor_sync(0xffffffffu, sm, o);
    float lse = mx + __logf(sm);
    out[(size_t)gw * OUTC + lane] = z0 - lse;
    if (v1) out[(size_t)gw * OUTC + 32 + lane] = z1 - lse;
}

// ---------------- launch -----------------------------------------------------
static inline int cdiv(long long a, int b) { return (int)((a + b - 1) / b); }

extern "C" void kernel_launch(void* const* d_in, const int* in_sizes, int n_in,
                              void* d_out, int out_size) {
    const float* x    = (const float*)d_in[0];
    const int*   ei   = (const int*)d_in[1];   // int32 (JAX x64 disabled)
    // d_in[2] = new_edge_indexs — unused by the reference
    const float* W1   = (const float*)d_in[3];
    const float* asr1 = (const float*)d_in[4];
    const float* ads1 = (const float*)d_in[5];
    const float* b1   = (const float*)d_in[6];
    const float* W2   = (const float*)d_in[7];
    const float* asr2 = (const float*)d_in[8];
    const float* ads2 = (const float*)d_in[9];
    const float* b2   = (const float*)d_in[10];
    float* out = (float*)d_out;

    float *h1, *h2, *agg1, *agg2, *as1, *ad1, *as2, *ad2;
    cudaGetSymbolAddress((void**)&h1, g_h1);
    cudaGetSymbolAddress((void**)&h2, g_h2);
    cudaGetSymbolAddress((void**)&agg1, g_agg1);
    cudaGetSymbolAddress((void**)&agg2, g_agg2);
    cudaGetSymbolAddress((void**)&as1, g_as1);
    cudaGetSymbolAddress((void**)&ad1, g_ad1);
    cudaGetSymbolAddress((void**)&as2, g_as2);
    cudaGetSymbolAddress((void**)&ad2, g_ad2);

    const int T = 256;

    // ---- CSR build (once, reused by both layers) ----
    k_zero<<<cdiv(NN, T), T>>>();
    k_hist<<<cdiv(EE, T), T>>>(ei);
    k_scan<<<1, 1024>>>();
    k_fill<<<cdiv(EE, T), T>>>(ei);

    // ---- layer 1 ----
    k_gemm_t<INC, HID, 64, 24, 8, false>
        <<<cdiv(NN, 64), 24 * 8>>>(x, W1, nullptr, asr1, ads1, as1, ad1, h1, NN);
    k_agg_csr<HID><<<cdiv(NN, 8), 256>>>(h1, as1, ad1, agg1);

    // ---- layer 2 ----
    k_gemm_t<HID, OUTC, 128, 10, 16, true>
        <<<cdiv(NN, 128), 10 * 16>>>(agg1, W2, b1, asr2, ads2, as2, ad2, h2, NN);
    k_agg_csr<OUTC><<<cdiv(NN, 8), 256>>>(h2, as2, ad2, agg2);
    k_out<<<cdiv((long long)NN * 32, T), T>>>(agg2, b2, out);
}

// round 8
// speedup vs baseline: 1.3352x; 1.2576x over previous
#include <cuda_runtime.h>

#define NN   50000
#define EE   800000
#define INC  128
#define HID  96
#define OUTC 40
#define SLOPE 0.2f

#define SCAN_B 1024
#define SCAN_NB ((NN + SCAN_B - 1) / SCAN_B)

// ---------------- scratch (device globals; no allocation allowed) ----------
__device__ float g_h1[(size_t)NN * HID];
__device__ float g_h2[(size_t)NN * OUTC];
__device__ float g_agg1[(size_t)NN * HID];   // normalized layer-1 aggregation
__device__ float g_agg2[(size_t)NN * OUTC];  // normalized layer-2 aggregation
__device__ float g_as1[NN], g_ad1[NN];
__device__ float g_as2[NN], g_ad2[NN];
__device__ int   g_cnt[NN];
__device__ int   g_off[NN + 1];
__device__ int   g_cur[NN];
__device__ int   g_part[SCAN_NB];
__device__ int   g_csr[EE];

// ---------------- zero pass --------------------------------------------------
__global__ void k_zero() {
    int i = blockIdx.x * blockDim.x + threadIdx.x;
    if (i < NN) {
        g_cnt[i] = 0;
        g_as1[i] = 0.f; g_ad1[i] = 0.f;
        g_as2[i] = 0.f; g_ad2[i] = 0.f;
    }
}

// ---------------- CSR build --------------------------------------------------
__global__ void k_hist(const int* __restrict__ ei) {
    int i = blockIdx.x * blockDim.x + threadIdx.x;
    if (i < EE) atomicAdd(&g_cnt[ei[EE + i]], 1);
}

__global__ void k_scan1() {
    __shared__ int sm[SCAN_B];
    int tid = threadIdx.x;
    int g = blockIdx.x * SCAN_B + tid;
    int v = (g < NN) ? g_cnt[g] : 0;
    sm[tid] = v;
    __syncthreads();
#pragma unroll
    for (int ofs = 1; ofs < SCAN_B; ofs <<= 1) {
        int t = (tid >= ofs) ? sm[tid - ofs] : 0;
        __syncthreads();
        sm[tid] += t;
        __syncthreads();
    }
    if (g < NN) g_off[g] = sm[tid] - v;     // exclusive within block
    if (tid == SCAN_B - 1) g_part[blockIdx.x] = sm[tid];
}

// parallel Hillis-Steele over the 49 block partials
__global__ void k_scan2() {
    __shared__ int sm[64];
    int tid = threadIdx.x;
    int v = (tid < SCAN_NB) ? g_part[tid] : 0;
    sm[tid] = v;
    __syncthreads();
#pragma unroll
    for (int o = 1; o < 64; o <<= 1) {
        int t = (tid >= o) ? sm[tid - o] : 0;
        __syncthreads();
        sm[tid] += t;
        __syncthreads();
    }
    if (tid < SCAN_NB) g_part[tid] = sm[tid] - v;   // exclusive
}

__global__ void k_scan3() {
    int g = blockIdx.x * SCAN_B + threadIdx.x;
    if (g < NN) {
        int o = g_off[g] + g_part[blockIdx.x];
        g_off[g] = o;
        g_cur[g] = o;
    }
    if (g == 0) g_off[NN] = EE;
}

__global__ void k_fill(const int* __restrict__ ei) {
    int i = blockIdx.x * blockDim.x + threadIdx.x;
    if (i >= EE) return;
    int d = ei[EE + i];
    int pos = atomicAdd(&g_cur[d], 1);
    g_csr[pos] = ei[i];
}

// ---------------- tiled GEMM: H[n,CO] = X[n,K] @ W[K,CO] --------------------
// Epilogue fuses per-node attention scalars (atomicAdd partials).
// Optional fused relu(x + bias) on the X-tile load (layer-2 input).
template <int K, int CO, int TM, int TCOLS, int TROWS, bool FUSE>
__global__ void k_gemm_t(const float* __restrict__ X, const float* __restrict__ W,
                         const float* __restrict__ bias,
                         const float* __restrict__ asrc, const float* __restrict__ adst,
                         float* __restrict__ oas, float* __restrict__ oad,
                         float* __restrict__ H, int n) {
    constexpr int KT = 32;
    constexpr int THREADS = TCOLS * TROWS;
    constexpr int RPT = TM / TROWS;
    __shared__ float Xs[TM][KT];
    __shared__ float Ws[KT][CO];

    const int tid  = threadIdx.x;
    const int tcol = tid % TCOLS;
    const int trow = tid / TCOLS;
    const int row0 = blockIdx.x * TM;

    float4 acc[RPT];
#pragma unroll
    for (int i = 0; i < RPT; i++) acc[i] = make_float4(0.f, 0.f, 0.f, 0.f);

    for (int kt = 0; kt < K; kt += KT) {
        for (int idx = tid; idx < TM * (KT / 4); idx += THREADS) {
            int r  = idx / (KT / 4);
            int c4 = idx % (KT / 4);
            int grow = row0 + r;
            float4 v = make_float4(0.f, 0.f, 0.f, 0.f);
            if (grow < n) {
                v = *(const float4*)(X + (size_t)grow * K + kt + c4 * 4);
                if constexpr (FUSE) {
                    const float* bb = bias + kt + c4 * 4;
                    v.x = fmaxf(v.x + bb[0], 0.f);
                    v.y = fmaxf(v.y + bb[1], 0.f);
                    v.z = fmaxf(v.z + bb[2], 0.f);
                    v.w = fmaxf(v.w + bb[3], 0.f);
                }
            }
            *(float4*)&Xs[r][c4 * 4] = v;
        }
        for (int idx = tid; idx < KT * (CO / 4); idx += THREADS) {
            int r  = idx / (CO / 4);
            int c4 = idx % (CO / 4);
            *(float4*)&Ws[r][c4 * 4] =
                *(const float4*)(W + (size_t)(kt + r) * CO + c4 * 4);
        }
        __syncthreads();

#pragma unroll
        for (int k4 = 0; k4 < KT; k4 += 4) {
            float4 xs[RPT];
#pragma unroll
            for (int i = 0; i < RPT; i++)
                xs[i] = *(float4*)&Xs[trow * RPT + i][k4];
#pragma unroll
            for (int kk = 0; kk < 4; kk++) {
                float4 w = *(float4*)&Ws[k4 + kk][tcol * 4];
#pragma unroll
                for (int i = 0; i < RPT; i++) {
                    float xv = (kk == 0) ? xs[i].x : (kk == 1) ? xs[i].y
                             : (kk == 2) ? xs[i].z : xs[i].w;
                    acc[i].x += xv * w.x; acc[i].y += xv * w.y;
                    acc[i].z += xv * w.z; acc[i].w += xv * w.w;
                }
            }
        }
        __syncthreads();
    }

    float4 vs = *(const float4*)(asrc + tcol * 4);
    float4 vd = *(const float4*)(adst + tcol * 4);
#pragma unroll
    for (int i = 0; i < RPT; i++) {
        int grow = row0 + trow * RPT + i;
        if (grow < n) {
            *(float4*)(H + (size_t)grow * CO + tcol * 4) = acc[i];
            float ps = acc[i].x * vs.x + acc[i].y * vs.y + acc[i].z * vs.z + acc[i].w * vs.w;
            float pd = acc[i].x * vd.x + acc[i].y * vd.y + acc[i].z * vd.z + acc[i].w * vd.w;
            atomicAdd(&oas[grow], ps);
            atomicAdd(&oad[grow], pd);
        }
    }
}

// ---------------- CSR gather aggregation: one warp per dst node --------------
// float4 lanes: lanes 0..C/4-1 each own 4 channels -> 1 LDG.128 per neighbor.
// out[node] = (w_self*h[node] + sum_e w_e*h[src_e]) / (w_self + sum_e w_e)
template <int C>
__global__ void k_agg_csr(const float* __restrict__ h,
                          const float* __restrict__ as,
                          const float* __restrict__ ad,
                          float* __restrict__ aggout) {
    constexpr int V4 = C / 4;            // active gather lanes (24 or 10)
    int node = blockIdx.x * (blockDim.x >> 5) + (threadIdx.x >> 5);
    int lane = threadIdx.x & 31;
    if (node >= NN) return;

    float ad_n = ad[node];
    float vself = as[node] + ad_n;
    vself = (vself > 0.f) ? vself : SLOPE * vself;
    float wself = __expf(vself);

    float4 acc = make_float4(0.f, 0.f, 0.f, 0.f);
    if (lane < V4) {
        float4 hv = *(const float4*)(h + (size_t)node * C + lane * 4);
        acc.x = wself * hv.x; acc.y = wself * hv.y;
        acc.z = wself * hv.z; acc.w = wself * hv.w;
    }

    int beg = g_off[node];
    int end = g_off[node + 1];
    float sloc = 0.f;

    for (int base = beg; base < end; base += 32) {
        int e = base + lane;
        bool valid = e < end;
        int src = valid ? g_csr[e] : 0;
        float w = 0.f;
        if (valid) {
            float v = as[src] + ad_n;
            v = (v > 0.f) ? v : SLOPE * v;
            w = __expf(v);
        }
        sloc += w;
        int cnt = min(32, end - base);
        for (int k = 0; k < cnt; k++) {
            float wk = __shfl_sync(0xffffffffu, w, k);
            int   sk = __shfl_sync(0xffffffffu, src, k);
            if (lane < V4) {
                float4 hv = *(const float4*)(h + (size_t)sk * C + lane * 4);
                acc.x += wk * hv.x; acc.y += wk * hv.y;
                acc.z += wk * hv.z; acc.w += wk * hv.w;
            }
        }
    }

#pragma unroll
    for (int o = 16; o; o >>= 1) sloc += __shfl_xor_sync(0xffffffffu, sloc, o);
    float inv = 1.f / (sloc + wself);

    if (lane < V4) {
        float4 r = make_float4(acc.x * inv, acc.y * inv, acc.z * inv, acc.w * inv);
        *(float4*)(aggout + (size_t)node * C + lane * 4) = r;
    }
}

// ---------------- bias + log_softmax (final output), one warp per node ------
__global__ void k_out(const float* __restrict__ agg, const float* __restrict__ b,
                      float* __restrict__ out) {
    int gw = (blockIdx.x * blockDim.x + threadIdx.x) >> 5;
    int lane = threadIdx.x & 31;
    if (gw >= NN) return;
    const float* row = agg + (size_t)gw * OUTC;
    float z0 = row[lane] + b[lane];
    bool v1 = lane < (OUTC - 32);
    float z1 = v1 ? (row[32 + lane] + b[32 + lane]) : -3.4e38f;
    float mx = fmaxf(z0, z1);
#pragma unroll
    for (int o = 16; o; o >>= 1) mx = fmaxf(mx, __shfl_xor_sync(0xffffffffu, mx, o));
    float sm = __expf(z0 - mx) + (v1 ? __expf(z1 - mx) : 0.f);
#pragma unroll
    for (int o = 16; o; o >>= 1) sm += __shfl_xor_sync(0xffffffffu, sm, o);
    float lse = mx + __logf(sm);
    out[(size_t)gw * OUTC + lane] = z0 - lse;
    if (v1) out[(size_t)gw * OUTC + 32 + lane] = z1 - lse;
}

// ---------------- launch -----------------------------------------------------
static inline int cdiv(long long a, int b) { return (int)((a + b - 1) / b); }

extern "C" void kernel_launch(void* const* d_in, const int* in_sizes, int n_in,
                              void* d_out, int out_size) {
    const float* x    = (const float*)d_in[0];
    const int*   ei   = (const int*)d_in[1];   // int32 (JAX x64 disabled)
    // d_in[2] = new_edge_indexs — unused by the reference
    const float* W1   = (const float*)d_in[3];
    const float* asr1 = (const float*)d_in[4];
    const float* ads1 = (const float*)d_in[5];
    const float* b1   = (const float*)d_in[6];
    const float* W2   = (const float*)d_in[7];
    const float* asr2 = (const float*)d_in[8];
    const float* ads2 = (const float*)d_in[9];
    const float* b2   = (const float*)d_in[10];
    float* out = (float*)d_out;

    float *h1, *h2, *agg1, *agg2, *as1, *ad1, *as2, *ad2;
    cudaGetSymbolAddress((void**)&h1, g_h1);
    cudaGetSymbolAddress((void**)&h2, g_h2);
    cudaGetSymbolAddress((void**)&agg1, g_agg1);
    cudaGetSymbolAddress((void**)&agg2, g_agg2);
    cudaGetSymbolAddress((void**)&as1, g_as1);
    cudaGetSymbolAddress((void**)&ad1, g_ad1);
    cudaGetSymbolAddress((void**)&as2, g_as2);
    cudaGetSymbolAddress((void**)&ad2, g_ad2);

    const int T = 256;

    // ---- CSR build (once, reused by both layers) ----
    k_zero<<<cdiv(NN, T), T>>>();
    k_hist<<<cdiv(EE, T), T>>>(ei);
    k_scan1<<<SCAN_NB, SCAN_B>>>();
    k_scan2<<<1, 64>>>();
    k_scan3<<<SCAN_NB, SCAN_B>>>();
    k_fill<<<cdiv(EE, T), T>>>(ei);

    // ---- layer 1 ----
    k_gemm_t<INC, HID, 64, 24, 8, false>
        <<<cdiv(NN, 64), 24 * 8>>>(x, W1, nullptr, asr1, ads1, as1, ad1, h1, NN);
    k_agg_csr<HID><<<cdiv(NN, 8), 256>>>(h1, as1, ad1, agg1);

    // ---- layer 2 ----
    k_gemm_t<HID, OUTC, 128, 10, 16, true>
        <<<cdiv(NN, 128), 10 * 16>>>(agg1, W2, b1, asr2, ads2, as2, ad2, h2, NN);
    k_agg_csr<OUTC><<<cdiv(NN, 8), 256>>>(h2, as2, ad2, agg2);
    k_out<<<cdiv((long long)NN * 32, T), T>>>(agg2, b2, out);
}

// round 9
// speedup vs baseline: 1.5727x; 1.1778x over previous
#include <cuda_runtime.h>

#define NN   50000
#define EE   800000
#define INC  128
#define HID  96
#define OUTC 40
#define SLOPE 0.2f

#define SCAN_B 1024
#define SCAN_NB ((NN + SCAN_B - 1) / SCAN_B)

// ---------------- scratch (device globals; no allocation allowed) ----------
__device__ float g_h1[(size_t)NN * HID];
__device__ float g_h2[(size_t)NN * OUTC];
__device__ float g_agg1[(size_t)NN * HID];   // normalized layer-1 aggregation
__device__ float g_as1[NN], g_ad1[NN];
__device__ float g_as2[NN], g_ad2[NN];
__device__ int   g_cnt[NN];
__device__ int   g_off[NN + 1];
__device__ int   g_cur[NN];
__device__ int   g_part[SCAN_NB];
__device__ int   g_csr[EE];

// ---------------- zero pass (everything, before fork) ------------------------
__global__ void k_zero() {
    int i = blockIdx.x * blockDim.x + threadIdx.x;
    if (i < NN) {
        g_cnt[i] = 0;
        g_as1[i] = 0.f; g_ad1[i] = 0.f;
        g_as2[i] = 0.f; g_ad2[i] = 0.f;
    }
}

// ---------------- CSR build --------------------------------------------------
__global__ void k_hist(const int* __restrict__ ei) {
    int i = blockIdx.x * blockDim.x + threadIdx.x;
    if (i < EE) atomicAdd(&g_cnt[ei[EE + i]], 1);
}

__global__ void k_scan1() {
    __shared__ int sm[SCAN_B];
    int tid = threadIdx.x;
    int g = blockIdx.x * SCAN_B + tid;
    int v = (g < NN) ? g_cnt[g] : 0;
    sm[tid] = v;
    __syncthreads();
#pragma unroll
    for (int ofs = 1; ofs < SCAN_B; ofs <<= 1) {
        int t = (tid >= ofs) ? sm[tid - ofs] : 0;
        __syncthreads();
        sm[tid] += t;
        __syncthreads();
    }
    if (g < NN) g_off[g] = sm[tid] - v;     // exclusive within block
    if (tid == SCAN_B - 1) g_part[blockIdx.x] = sm[tid];
}

// parallel Hillis-Steele over the 49 block partials
__global__ void k_scan2() {
    __shared__ int sm[64];
    int tid = threadIdx.x;
    int v = (tid < SCAN_NB) ? g_part[tid] : 0;
    sm[tid] = v;
    __syncthreads();
#pragma unroll
    for (int o = 1; o < 64; o <<= 1) {
        int t = (tid >= o) ? sm[tid - o] : 0;
        __syncthreads();
        sm[tid] += t;
        __syncthreads();
    }
    if (tid < SCAN_NB) g_part[tid] = sm[tid] - v;   // exclusive
}

__global__ void k_scan3() {
    int g = blockIdx.x * SCAN_B + threadIdx.x;
    if (g < NN) {
        int o = g_off[g] + g_part[blockIdx.x];
        g_off[g] = o;
        g_cur[g] = o;
    }
    if (g == 0) g_off[NN] = EE;
}

__global__ void k_fill(const int* __restrict__ ei) {
    int i = blockIdx.x * blockDim.x + threadIdx.x;
    if (i >= EE) return;
    int d = ei[EE + i];
    int pos = atomicAdd(&g_cur[d], 1);
    g_csr[pos] = ei[i];
}

// ---------------- tiled GEMM: H[n,CO] = X[n,K] @ W[K,CO] --------------------
// Epilogue fuses per-node attention scalars (atomicAdd partials).
// Optional fused relu(x + bias) on the X-tile load (layer-2 input).
template <int K, int CO, int TM, int TCOLS, int TROWS, bool FUSE>
__global__ void k_gemm_t(const float* __restrict__ X, const float* __restrict__ W,
                         const float* __restrict__ bias,
                         const float* __restrict__ asrc, const float* __restrict__ adst,
                         float* __restrict__ oas, float* __restrict__ oad,
                         float* __restrict__ H, int n) {
    constexpr int KT = 32;
    constexpr int THREADS = TCOLS * TROWS;
    constexpr int RPT = TM / TROWS;
    __shared__ float Xs[TM][KT];
    __shared__ float Ws[KT][CO];

    const int tid  = threadIdx.x;
    const int tcol = tid % TCOLS;
    const int trow = tid / TCOLS;
    const int row0 = blockIdx.x * TM;

    float4 acc[RPT];
#pragma unroll
    for (int i = 0; i < RPT; i++) acc[i] = make_float4(0.f, 0.f, 0.f, 0.f);

    for (int kt = 0; kt < K; kt += KT) {
        for (int idx = tid; idx < TM * (KT / 4); idx += THREADS) {
            int r  = idx / (KT / 4);
            int c4 = idx % (KT / 4);
            int grow = row0 + r;
            float4 v = make_float4(0.f, 0.f, 0.f, 0.f);
            if (grow < n) {
                v = *(const float4*)(X + (size_t)grow * K + kt + c4 * 4);
                if constexpr (FUSE) {
                    const float* bb = bias + kt + c4 * 4;
                    v.x = fmaxf(v.x + bb[0], 0.f);
                    v.y = fmaxf(v.y + bb[1], 0.f);
                    v.z = fmaxf(v.z + bb[2], 0.f);
                    v.w = fmaxf(v.w + bb[3], 0.f);
                }
            }
            *(float4*)&Xs[r][c4 * 4] = v;
        }
        for (int idx = tid; idx < KT * (CO / 4); idx += THREADS) {
            int r  = idx / (CO / 4);
            int c4 = idx % (CO / 4);
            *(float4*)&Ws[r][c4 * 4] =
                *(const float4*)(W + (size_t)(kt + r) * CO + c4 * 4);
        }
        __syncthreads();

#pragma unroll
        for (int k4 = 0; k4 < KT; k4 += 4) {
            float4 xs[RPT];
#pragma unroll
            for (int i = 0; i < RPT; i++)
                xs[i] = *(float4*)&Xs[trow * RPT + i][k4];
#pragma unroll
            for (int kk = 0; kk < 4; kk++) {
                float4 w = *(float4*)&Ws[k4 + kk][tcol * 4];
#pragma unroll
                for (int i = 0; i < RPT; i++) {
                    float xv = (kk == 0) ? xs[i].x : (kk == 1) ? xs[i].y
                             : (kk == 2) ? xs[i].z : xs[i].w;
                    acc[i].x += xv * w.x; acc[i].y += xv * w.y;
                    acc[i].z += xv * w.z; acc[i].w += xv * w.w;
                }
            }
        }
        __syncthreads();
    }

    float4 vs = *(const float4*)(asrc + tcol * 4);
    float4 vd = *(const float4*)(adst + tcol * 4);
#pragma unroll
    for (int i = 0; i < RPT; i++) {
        int grow = row0 + trow * RPT + i;
        if (grow < n) {
            *(float4*)(H + (size_t)grow * CO + tcol * 4) = acc[i];
            float ps = acc[i].x * vs.x + acc[i].y * vs.y + acc[i].z * vs.z + acc[i].w * vs.w;
            float pd = acc[i].x * vd.x + acc[i].y * vd.y + acc[i].z * vd.z + acc[i].w * vd.w;
            atomicAdd(&oas[grow], ps);
            atomicAdd(&oad[grow], pd);
        }
    }
}

// ---------------- CSR gather aggregation: one warp per dst node --------------
// Scalar lanes (R5 form): channel c = lane + 32*j.
// out[node] = (w_self*h[node] + sum_e w_e*h[src_e]) / (w_self + sum_e w_e)
// FINAL: fuse bias + log_softmax and write the final output row.
template <int C, bool FINAL>
__global__ void k_agg_csr(const float* __restrict__ h,
                          const float* __restrict__ as,
                          const float* __restrict__ ad,
                          const float* __restrict__ bias,
                          float* __restrict__ aggout) {
    constexpr int CPL = (C + 31) / 32;   // channels per lane
    int node = blockIdx.x * (blockDim.x >> 5) + (threadIdx.x >> 5);
    int lane = threadIdx.x & 31;
    if (node >= NN) return;

    float ad_n = ad[node];
    float vself = as[node] + ad_n;
    vself = (vself > 0.f) ? vself : SLOPE * vself;
    float wself = __expf(vself);

    float acc[CPL];
#pragma unroll
    for (int j = 0; j < CPL; j++) {
        int c = lane + 32 * j;
        acc[j] = (c < C) ? wself * h[(size_t)node * C + c] : 0.f;
    }

    int beg = g_off[node];
    int end = g_off[node + 1];
    float sloc = 0.f;

    for (int base = beg; base < end; base += 32) {
        int e = base + lane;
        bool valid = e < end;
        int src = valid ? g_csr[e] : 0;
        float w = 0.f;
        if (valid) {
            float v = as[src] + ad_n;
            v = (v > 0.f) ? v : SLOPE * v;
            w = __expf(v);
        }
        sloc += w;
        int cnt = min(32, end - base);
        for (int k = 0; k < cnt; k++) {
            float wk = __shfl_sync(0xffffffffu, w, k);
            int   sk = __shfl_sync(0xffffffffu, src, k);
            const float* hr = h + (size_t)sk * C;
#pragma unroll
            for (int j = 0; j < CPL; j++) {
                int c = lane + 32 * j;
                if (c < C) acc[j] += wk * hr[c];
            }
        }
    }

#pragma unroll
    for (int o = 16; o; o >>= 1) sloc += __shfl_xor_sync(0xffffffffu, sloc, o);
    float inv = 1.f / (sloc + wself);

    if constexpr (!FINAL) {
#pragma unroll
        for (int j = 0; j < CPL; j++) {
            int c = lane + 32 * j;
            if (c < C) aggout[(size_t)node * C + c] = acc[j] * inv;
        }
    } else {
        float z[CPL];
        float mx = -3.4e38f;
#pragma unroll
        for (int j = 0; j < CPL; j++) {
            int c = lane + 32 * j;
            z[j] = (c < C) ? (acc[j] * inv + bias[c]) : -3.4e38f;
            mx = fmaxf(mx, z[j]);
        }
#pragma unroll
        for (int o = 16; o; o >>= 1) mx = fmaxf(mx, __shfl_xor_sync(0xffffffffu, mx, o));
        float sm = 0.f;
#pragma unroll
        for (int j = 0; j < CPL; j++) {
            int c = lane + 32 * j;
            if (c < C) sm += __expf(z[j] - mx);
        }
#pragma unroll
        for (int o = 16; o; o >>= 1) sm += __shfl_xor_sync(0xffffffffu, sm, o);
        float lse = mx + __logf(sm);
#pragma unroll
        for (int j = 0; j < CPL; j++) {
            int c = lane + 32 * j;
            if (c < C) aggout[(size_t)node * C + c] = z[j] - lse;
        }
    }
}

// ---------------- launch -----------------------------------------------------
static inline int cdiv(long long a, int b) { return (int)((a + b - 1) / b); }

extern "C" void kernel_launch(void* const* d_in, const int* in_sizes, int n_in,
                              void* d_out, int out_size) {
    const float* x    = (const float*)d_in[0];
    const int*   ei   = (const int*)d_in[1];   // int32 (JAX x64 disabled)
    // d_in[2] = new_edge_indexs — unused by the reference
    const float* W1   = (const float*)d_in[3];
    const float* asr1 = (const float*)d_in[4];
    const float* ads1 = (const float*)d_in[5];
    const float* b1   = (const float*)d_in[6];
    const float* W2   = (const float*)d_in[7];
    const float* asr2 = (const float*)d_in[8];
    const float* ads2 = (const float*)d_in[9];
    const float* b2   = (const float*)d_in[10];
    float* out = (float*)d_out;

    float *h1, *h2, *agg1, *as1, *ad1, *as2, *ad2;
    cudaGetSymbolAddress((void**)&h1, g_h1);
    cudaGetSymbolAddress((void**)&h2, g_h2);
    cudaGetSymbolAddress((void**)&agg1, g_agg1);
    cudaGetSymbolAddress((void**)&as1, g_as1);
    cudaGetSymbolAddress((void**)&ad1, g_ad1);
    cudaGetSymbolAddress((void**)&as2, g_as2);
    cudaGetSymbolAddress((void**)&ad2, g_ad2);

    // one-time side stream + events (host resources only; identical GPU work
    // per call, captured via the standard fork/join event pattern)
    static cudaStream_t s2 = nullptr;
    static cudaEvent_t evFork = nullptr, evJoin = nullptr;
    if (!s2) {
        cudaStreamCreateWithFlags(&s2, cudaStreamNonBlocking);
        cudaEventCreateWithFlags(&evFork, cudaEventDisableTiming);
        cudaEventCreateWithFlags(&evJoin, cudaEventDisableTiming);
    }

    const int T = 256;

    // ---- zero everything first (main stream), then fork ---------------------
    k_zero<<<cdiv(NN, T), T>>>();
    cudaEventRecord(evFork, 0);
    cudaStreamWaitEvent(s2, evFork, 0);

    // side stream: CSR build
    k_hist<<<cdiv(EE, T), T, 0, s2>>>(ei);
    k_scan1<<<SCAN_NB, SCAN_B, 0, s2>>>();
    k_scan2<<<1, 64, 0, s2>>>();
    k_scan3<<<SCAN_NB, SCAN_B, 0, s2>>>();
    k_fill<<<cdiv(EE, T), T, 0, s2>>>(ei);
    cudaEventRecord(evJoin, s2);

    // main stream: GEMM1 (overlaps the CSR build)
    k_gemm_t<INC, HID, 64, 24, 8, false>
        <<<cdiv(NN, 64), 24 * 8>>>(x, W1, nullptr, asr1, ads1, as1, ad1, h1, NN);

    // join: aggregation needs both GEMM1 (main) and CSR (s2)
    cudaStreamWaitEvent(0, evJoin, 0);
    k_agg_csr<HID, false><<<cdiv(NN, 8), 256>>>(h1, as1, ad1, nullptr, agg1);

    // ---- layer 2 ----
    k_gemm_t<HID, OUTC, 128, 10, 16, true>
        <<<cdiv(NN, 128), 10 * 16>>>(agg1, W2, b1, asr2, ads2, as2, ad2, h2, NN);
    k_agg_csr<OUTC, true><<<cdiv(NN, 8), 256>>>(h2, as2, ad2, b2, out);
}